// round 5
// baseline (speedup 1.0000x reference)
#include <cuda_runtime.h>
#include <cstdint>

#define NTOK  343
#define NHEAD 8
#define CDIM  256
#define HD    32
#define BWIN  256
#define NWND  64
#define QSCALE 0.17677669529663687f   // 32^-0.5

// ---------------- scratch (device globals: no allocation allowed) ----------------
__device__ float g_q[(size_t)BWIN * NHEAD * NTOK * HD];   // scaled q, (Bw,H,n,hd)
__device__ float g_k[(size_t)BWIN * NHEAD * NTOK * HD];
__device__ float g_v[(size_t)BWIN * NHEAD * NTOK * HD];
__device__ float g_o[(size_t)BWIN * NTOK * CDIM];         // attention out, (Bw,n,C)

// =================================================================================
// Kernel 1: QKV = x @ qkv_w + qkv_b, scatter to g_q (scaled), g_k, g_v
// A: (87808 x 256), B: (256 x 768). Tiles: BM=128, BN=128, BK=8, 256 threads, 8x8.
// =================================================================================
__global__ __launch_bounds__(256) void qkv_gemm_kernel(
    const float* __restrict__ x,
    const float* __restrict__ w,
    const float* __restrict__ bias)
{
    __shared__ float As[8][132];
    __shared__ float Bs[8][132];

    const int tid = threadIdx.x;
    const int tx  = tid & 15;      // n direction (16)
    const int ty  = tid >> 4;      // m direction (16)
    const int m0  = blockIdx.x * 128;
    const int n0  = blockIdx.y * 128;

    const int arow = tid >> 1;            // 0..127
    const int akg  = (tid & 1) * 4;       // 0 or 4
    const int brow = tid >> 5;            // 0..7
    const int bc   = (tid & 31) * 4;      // 0..124

    const float* ap = x + (size_t)(m0 + arow) * 256 + akg;
    const float* bp = w + (size_t)brow * 768 + n0 + bc;

    float acc[8][8];
    #pragma unroll
    for (int u = 0; u < 8; u++)
        #pragma unroll
        for (int v = 0; v < 8; v++) acc[u][v] = 0.f;

    for (int k0 = 0; k0 < 256; k0 += 8) {
        float4 av = *(const float4*)(ap + k0);
        float4 bv = *(const float4*)(bp + (size_t)k0 * 768);
        As[akg + 0][arow] = av.x;
        As[akg + 1][arow] = av.y;
        As[akg + 2][arow] = av.z;
        As[akg + 3][arow] = av.w;
        *(float4*)&Bs[brow][bc] = bv;
        __syncthreads();

        #pragma unroll
        for (int kk = 0; kk < 8; kk++) {
            float a[8], b[8];
            *(float4*)(a)     = *(const float4*)&As[kk][ty * 8];
            *(float4*)(a + 4) = *(const float4*)&As[kk][ty * 8 + 4];
            *(float4*)(b)     = *(const float4*)&Bs[kk][tx * 8];
            *(float4*)(b + 4) = *(const float4*)&Bs[kk][tx * 8 + 4];
            #pragma unroll
            for (int u = 0; u < 8; u++)
                #pragma unroll
                for (int v = 0; v < 8; v++) acc[u][v] += a[u] * b[v];
        }
        __syncthreads();
    }

    // epilogue: bias, scale q, scatter to (Bw,H,n,hd)
    #pragma unroll
    for (int u = 0; u < 8; u++) {
        const int r  = m0 + ty * 8 + u;
        const int bw = r / NTOK;
        const int i  = r - bw * NTOK;
        #pragma unroll
        for (int v0 = 0; v0 < 8; v0 += 4) {
            const int c    = n0 + tx * 8 + v0;
            const int part = c >> 8;          // uniform per block (n0 multiple of 128)
            const int cc   = c & 255;
            const int h    = cc >> 5;
            const int d    = cc & 31;
            float4 vv;
            vv.x = acc[u][v0 + 0] + bias[c + 0];
            vv.y = acc[u][v0 + 1] + bias[c + 1];
            vv.z = acc[u][v0 + 2] + bias[c + 2];
            vv.w = acc[u][v0 + 3] + bias[c + 3];
            float* dst;
            if (part == 0) {
                vv.x *= QSCALE; vv.y *= QSCALE; vv.z *= QSCALE; vv.w *= QSCALE;
                dst = g_q;
            } else {
                dst = (part == 1) ? g_k : g_v;
            }
            *(float4*)&dst[(size_t)((bw * NHEAD + h) * NTOK + i) * HD + d] = vv;
        }
    }
}

// =================================================================================
// Kernel 2: fused attention. One block = one (bw, head). 512 threads (16 warps).
// smem: K(343x36), V(343x36), rpb column (2197), p-buffers (16x343).
// Each warp processes query rows i = warp, warp+16, ...
// =================================================================================
__global__ __launch_bounds__(512) void attn_kernel(
    const float* __restrict__ mask,
    const float* __restrict__ rpb,
    const int*   __restrict__ rel_idx)
{
    extern __shared__ float sm[];
    float* Ks  = sm;                      // 343*36
    float* Vs  = Ks + NTOK * 36;          // 343*36
    float* tab = Vs + NTOK * 36;          // 2197
    float* ps  = tab + 2197;              // 16*343

    const int bx = blockIdx.x;
    const int bw = bx >> 3;
    const int h  = bx & 7;
    const int tid = threadIdx.x;

    const float* kb = g_k + (size_t)(bw * NHEAD + h) * NTOK * HD;
    const float* vb = g_v + (size_t)(bw * NHEAD + h) * NTOK * HD;

    // ---- cooperative load of K, V (padded), rpb column ----
    for (int idx = tid; idx < NTOK * 8; idx += 512) {
        const int row = idx >> 3;
        const int c4  = idx & 7;
        float4 kv = ((const float4*)kb)[idx];
        *(float4*)&Ks[row * 36 + c4 * 4] = kv;
        float4 vv = ((const float4*)vb)[idx];
        *(float4*)&Vs[row * 36 + c4 * 4] = vv;
    }
    for (int idx = tid; idx < 2197; idx += 512) tab[idx] = rpb[idx * NHEAD + h];
    __syncthreads();

    const int warp = tid >> 5;
    const int lane = tid & 31;
    const int g    = lane >> 3;   // j-group (0..3)
    const int dq   = lane & 7;    // float4 index into head dim

    const float* qb   = g_q + (size_t)(bw * NHEAD + h) * NTOK * HD;
    const float* mrow = mask + (size_t)(bw & (NWND - 1)) * NTOK * NTOK;
    float*       po   = g_o + (size_t)bw * NTOK * CDIM + h * HD;
    float*       myps = ps + warp * NTOK;

    for (int i = warp; i < NTOK; i += 16) {
        // q row into registers (broadcast load)
        float4 qf[8];
        const float4* qp = (const float4*)(qb + i * HD);
        #pragma unroll
        for (int u = 0; u < 8; u++) qf[u] = qp[u];

        const int*   ri = rel_idx + i * NTOK;
        const float* mi = mrow + (size_t)i * NTOK;

        // ---- scores: lane handles j = lane + 32t ----
        float s[11];
        float mx = -1e30f;
        #pragma unroll
        for (int t = 0; t < 11; t++) {
            const int j = lane + 32 * t;
            float sc = -1e30f;
            if (j < NTOK) {
                const float* kr = &Ks[j * 36];
                float a0 = 0.f, a1 = 0.f, a2 = 0.f, a3 = 0.f;
                #pragma unroll
                for (int u = 0; u < 8; u++) {
                    float4 kv = *(const float4*)(kr + u * 4);
                    a0 += qf[u].x * kv.x;
                    a1 += qf[u].y * kv.y;
                    a2 += qf[u].z * kv.z;
                    a3 += qf[u].w * kv.w;
                }
                sc = (a0 + a1) + (a2 + a3);
                sc += tab[__ldg(ri + j)] + __ldg(mi + j);
            }
            s[t] = sc;
            mx = fmaxf(mx, sc);
        }
        #pragma unroll
        for (int off = 16; off; off >>= 1)
            mx = fmaxf(mx, __shfl_xor_sync(0xFFFFFFFFu, mx, off));

        float sum = 0.f;
        #pragma unroll
        for (int t = 0; t < 11; t++) {
            float p = exp2f((s[t] - mx) * 1.4426950408889634f);  // invalid j -> 0
            s[t] = p;
            sum += p;
        }
        #pragma unroll
        for (int off = 16; off; off >>= 1)
            sum += __shfl_xor_sync(0xFFFFFFFFu, sum, off);
        const float rinv = 1.f / sum;

        // stage probabilities in smem for the PV pass
        #pragma unroll
        for (int t = 0; t < 11; t++) {
            const int j = lane + 32 * t;
            if (j < NTOK) myps[j] = s[t];
        }
        __syncwarp();

        // ---- PV: 4 lane-groups over j, each lane accumulates a float4 of d ----
        float ax = 0.f, ay = 0.f, az = 0.f, aw = 0.f;
        #pragma unroll 5
        for (int jt = 0; jt < 85; jt++) {
            const int j = jt * 4 + g;              // j <= 339, always valid
            const float pj = myps[j];
            float4 v4 = *(const float4*)&Vs[j * 36 + dq * 4];
            ax += pj * v4.x; ay += pj * v4.y;
            az += pj * v4.z; aw += pj * v4.w;
        }
        {   // tail: j = 340..342 (g == 3 invalid)
            const int j = 340 + g;
            if (j < NTOK) {
                const float pj = myps[j];
                float4 v4 = *(const float4*)&Vs[j * 36 + dq * 4];
                ax += pj * v4.x; ay += pj * v4.y;
                az += pj * v4.z; aw += pj * v4.w;
            }
        }
        // combine the 4 j-groups
        ax += __shfl_xor_sync(0xFFFFFFFFu, ax, 8);
        ay += __shfl_xor_sync(0xFFFFFFFFu, ay, 8);
        az += __shfl_xor_sync(0xFFFFFFFFu, az, 8);
        aw += __shfl_xor_sync(0xFFFFFFFFu, aw, 8);
        ax += __shfl_xor_sync(0xFFFFFFFFu, ax, 16);
        ay += __shfl_xor_sync(0xFFFFFFFFu, ay, 16);
        az += __shfl_xor_sync(0xFFFFFFFFu, az, 16);
        aw += __shfl_xor_sync(0xFFFFFFFFu, aw, 16);

        if (lane < 8) {   // g == 0, dq == lane: write full head-dim row
            float4 outv = make_float4(ax * rinv, ay * rinv, az * rinv, aw * rinv);
            *(float4*)&po[(size_t)i * CDIM + dq * 4] = outv;
        }
        __syncwarp();   // protect myps before next row's writes
    }
}

// =================================================================================
// Kernel 3: out = g_o @ proj_w + proj_b. A: (87808 x 256), B: (256 x 256).
// =================================================================================
__global__ __launch_bounds__(256) void proj_gemm_kernel(
    const float* __restrict__ w,
    const float* __restrict__ bias,
    float* __restrict__ out)
{
    __shared__ float As[8][132];
    __shared__ float Bs[8][132];

    const int tid = threadIdx.x;
    const int tx  = tid & 15;
    const int ty  = tid >> 4;
    const int m0  = blockIdx.x * 128;
    const int n0  = blockIdx.y * 128;

    const int arow = tid >> 1;
    const int akg  = (tid & 1) * 4;
    const int brow = tid >> 5;
    const int bc   = (tid & 31) * 4;

    const float* ap = g_o + (size_t)(m0 + arow) * 256 + akg;
    const float* bp = w + (size_t)brow * 256 + n0 + bc;

    float acc[8][8];
    #pragma unroll
    for (int u = 0; u < 8; u++)
        #pragma unroll
        for (int v = 0; v < 8; v++) acc[u][v] = 0.f;

    for (int k0 = 0; k0 < 256; k0 += 8) {
        float4 av = *(const float4*)(ap + k0);
        float4 bv = *(const float4*)(bp + (size_t)k0 * 256);
        As[akg + 0][arow] = av.x;
        As[akg + 1][arow] = av.y;
        As[akg + 2][arow] = av.z;
        As[akg + 3][arow] = av.w;
        *(float4*)&Bs[brow][bc] = bv;
        __syncthreads();

        #pragma unroll
        for (int kk = 0; kk < 8; kk++) {
            float a[8], b[8];
            *(float4*)(a)     = *(const float4*)&As[kk][ty * 8];
            *(float4*)(a + 4) = *(const float4*)&As[kk][ty * 8 + 4];
            *(float4*)(b)     = *(const float4*)&Bs[kk][tx * 8];
            *(float4*)(b + 4) = *(const float4*)&Bs[kk][tx * 8 + 4];
            #pragma unroll
            for (int u = 0; u < 8; u++)
                #pragma unroll
                for (int v = 0; v < 8; v++) acc[u][v] += a[u] * b[v];
        }
        __syncthreads();
    }

    #pragma unroll
    for (int u = 0; u < 8; u++) {
        const int r = m0 + ty * 8 + u;
        #pragma unroll
        for (int v0 = 0; v0 < 8; v0 += 4) {
            const int c = n0 + tx * 8 + v0;
            float4 vv;
            vv.x = acc[u][v0 + 0] + bias[c + 0];
            vv.y = acc[u][v0 + 1] + bias[c + 1];
            vv.z = acc[u][v0 + 2] + bias[c + 2];
            vv.w = acc[u][v0 + 3] + bias[c + 3];
            *(float4*)&out[(size_t)r * 256 + c] = vv;
        }
    }
}

// =================================================================================
extern "C" void kernel_launch(void* const* d_in, const int* in_sizes, int n_in,
                              void* d_out, int out_size)
{
    const float* x       = (const float*)d_in[0];
    const float* mask    = (const float*)d_in[1];
    const float* qkv_w   = (const float*)d_in[2];
    const float* qkv_b   = (const float*)d_in[3];
    const float* proj_w  = (const float*)d_in[4];
    const float* proj_b  = (const float*)d_in[5];
    const float* rpb     = (const float*)d_in[6];
    const int*   rel_idx = (const int*)d_in[7];
    float* out = (float*)d_out;

    // 1) QKV projection + scatter
    qkv_gemm_kernel<<<dim3(686, 6), 256>>>(x, qkv_w, qkv_b);

    // 2) fused window attention
    const size_t smem_bytes =
        (size_t)(NTOK * 36 * 2 + 2197 + 16 * NTOK) * sizeof(float);  // ~129.5 KB
    cudaFuncSetAttribute(attn_kernel,
                         cudaFuncAttributeMaxDynamicSharedMemorySize,
                         (int)smem_bytes);
    attn_kernel<<<BWIN * NHEAD, 512, smem_bytes>>>(mask, rpb, rel_idx);

    // 3) output projection
    proj_gemm_kernel<<<dim3(686, 2), 256>>>(proj_w, proj_b, out);
}

// round 10
// speedup vs baseline: 1.3759x; 1.3759x over previous
#include <cuda_runtime.h>
#include <cstdint>

#define NTOK  343
#define NHEAD 8
#define CDIM  256
#define HD    32
#define BWIN  256
#define NWND  64
#define QSCALE 0.17677669529663687f   // 32^-0.5

// ---------------- scratch (device globals: no allocation allowed) ----------------
__device__ float g_q[(size_t)BWIN * NHEAD * NTOK * HD];   // scaled q, (Bw,H,n,hd)
__device__ float g_k[(size_t)BWIN * NHEAD * NTOK * HD];
__device__ float g_v[(size_t)BWIN * NHEAD * NTOK * HD];
__device__ float g_o[(size_t)BWIN * NTOK * CDIM];         // attention out, (Bw,n,C)

// =================================================================================
// Kernel 1: QKV = x @ qkv_w + qkv_b, scatter to g_q (scaled), g_k, g_v
// A: (87808 x 256), B: (256 x 768). BM=128, BN=128, BK=8 double-buffered, 256 thr.
// =================================================================================
__global__ __launch_bounds__(256) void qkv_gemm_kernel(
    const float* __restrict__ x,
    const float* __restrict__ w,
    const float* __restrict__ bias)
{
    __shared__ float As[2][8][132];
    __shared__ float Bs[2][8][132];

    const int tid = threadIdx.x;
    const int tx  = tid & 15;      // n direction (16)
    const int ty  = tid >> 4;      // m direction (16)
    const int m0  = blockIdx.x * 128;
    const int n0  = blockIdx.y * 128;

    const int arow = tid >> 1;            // 0..127
    const int akg  = (tid & 1) * 4;       // 0 or 4
    const int brow = tid >> 5;            // 0..7
    const int bc   = (tid & 31) * 4;      // 0..124

    const float* ap = x + (size_t)(m0 + arow) * 256 + akg;
    const float* bp = w + (size_t)brow * 768 + n0 + bc;

    float acc[8][8];
    #pragma unroll
    for (int u = 0; u < 8; u++)
        #pragma unroll
        for (int v = 0; v < 8; v++) acc[u][v] = 0.f;

    // prologue: load + stage k0 = 0
    {
        float4 av = *(const float4*)(ap);
        float4 bv = *(const float4*)(bp);
        As[0][akg + 0][arow] = av.x;
        As[0][akg + 1][arow] = av.y;
        As[0][akg + 2][arow] = av.z;
        As[0][akg + 3][arow] = av.w;
        *(float4*)&Bs[0][brow][bc] = bv;
    }
    __syncthreads();

    int cur = 0;
    for (int k0 = 0; k0 < 256; k0 += 8) {
        const bool has_next = (k0 + 8) < 256;
        float4 anx, bnx;
        if (has_next) {
            anx = *(const float4*)(ap + k0 + 8);
            bnx = *(const float4*)(bp + (size_t)(k0 + 8) * 768);
        }

        #pragma unroll
        for (int kk = 0; kk < 8; kk++) {
            float a[8], b[8];
            *(float4*)(a)     = *(const float4*)&As[cur][kk][ty * 8];
            *(float4*)(a + 4) = *(const float4*)&As[cur][kk][ty * 8 + 4];
            *(float4*)(b)     = *(const float4*)&Bs[cur][kk][tx * 8];
            *(float4*)(b + 4) = *(const float4*)&Bs[cur][kk][tx * 8 + 4];
            #pragma unroll
            for (int u = 0; u < 8; u++)
                #pragma unroll
                for (int v = 0; v < 8; v++) acc[u][v] += a[u] * b[v];
        }

        if (has_next) {
            const int nxt = cur ^ 1;
            As[nxt][akg + 0][arow] = anx.x;
            As[nxt][akg + 1][arow] = anx.y;
            As[nxt][akg + 2][arow] = anx.z;
            As[nxt][akg + 3][arow] = anx.w;
            *(float4*)&Bs[nxt][brow][bc] = bnx;
            __syncthreads();
            cur = nxt;
        }
    }

    // epilogue: bias, scale q, scatter to (Bw,H,n,hd)
    #pragma unroll
    for (int u = 0; u < 8; u++) {
        const int r  = m0 + ty * 8 + u;
        const int bw = r / NTOK;
        const int i  = r - bw * NTOK;
        #pragma unroll
        for (int v0 = 0; v0 < 8; v0 += 4) {
            const int c    = n0 + tx * 8 + v0;
            const int part = c >> 8;          // uniform per block (n0 multiple of 128)
            const int cc   = c & 255;
            const int h    = cc >> 5;
            const int d    = cc & 31;
            float4 vv;
            vv.x = acc[u][v0 + 0] + bias[c + 0];
            vv.y = acc[u][v0 + 1] + bias[c + 1];
            vv.z = acc[u][v0 + 2] + bias[c + 2];
            vv.w = acc[u][v0 + 3] + bias[c + 3];
            float* dst;
            if (part == 0) {
                vv.x *= QSCALE; vv.y *= QSCALE; vv.z *= QSCALE; vv.w *= QSCALE;
                dst = g_q;
            } else {
                dst = (part == 1) ? g_k : g_v;
            }
            *(float4*)&dst[(size_t)((bw * NHEAD + h) * NTOK + i) * HD + d] = vv;
        }
    }
}

// =================================================================================
// Kernel 2: fused attention, 2-row register blocking per warp.
// One block = one (bw, head). 512 threads (16 warps).
// smem: K(343x36), V(343x36), rpb column (2197), p-buffers (16 x 2 x 343).
// Warp w processes row pairs (2*ib, 2*ib+1) for ib = w, w+16, ...
// =================================================================================
__global__ __launch_bounds__(512) void attn_kernel(
    const float* __restrict__ mask,
    const float* __restrict__ rpb,
    const int*   __restrict__ rel_idx)
{
    extern __shared__ float sm[];
    float* Ks  = sm;                      // 343*36
    float* Vs  = Ks + NTOK * 36;          // 343*36
    float* tab = Vs + NTOK * 36;          // 2197
    float* ps  = tab + 2197;              // 16*2*343

    const int bx = blockIdx.x;
    const int bw = bx >> 3;
    const int h  = bx & 7;
    const int tid = threadIdx.x;

    const float* kb = g_k + (size_t)(bw * NHEAD + h) * NTOK * HD;
    const float* vb = g_v + (size_t)(bw * NHEAD + h) * NTOK * HD;

    // ---- cooperative load of K, V (padded), rpb column ----
    for (int idx = tid; idx < NTOK * 8; idx += 512) {
        const int row = idx >> 3;
        const int c4  = idx & 7;
        float4 kv = ((const float4*)kb)[idx];
        *(float4*)&Ks[row * 36 + c4 * 4] = kv;
        float4 vv = ((const float4*)vb)[idx];
        *(float4*)&Vs[row * 36 + c4 * 4] = vv;
    }
    for (int idx = tid; idx < 2197; idx += 512) tab[idx] = rpb[idx * NHEAD + h];
    __syncthreads();

    const int warp = tid >> 5;
    const int lane = tid & 31;
    const int g    = lane >> 3;   // j-group (0..3)
    const int dq   = lane & 7;    // float4 index into head dim

    const float* qb   = g_q + (size_t)(bw * NHEAD + h) * NTOK * HD;
    const float* mrow = mask + (size_t)(bw & (NWND - 1)) * NTOK * NTOK;
    float*       po   = g_o + (size_t)bw * NTOK * CDIM + h * HD;
    float*       ps0  = ps + warp * 2 * NTOK;
    float*       ps1  = ps0 + NTOK;

    for (int ib = warp; ib < (NTOK + 1) / 2; ib += 16) {
        const int i0  = 2 * ib;
        const int i1r = 2 * ib + 1;
        const bool valid1 = (i1r < NTOK);
        const int i1 = valid1 ? i1r : (NTOK - 1);

        // q rows into registers (broadcast loads)
        float4 q0[8], q1[8];
        {
            const float4* qp0 = (const float4*)(qb + i0 * HD);
            const float4* qp1 = (const float4*)(qb + i1 * HD);
            #pragma unroll
            for (int u = 0; u < 8; u++) { q0[u] = qp0[u]; q1[u] = qp1[u]; }
        }

        const int*   ri0 = rel_idx + i0 * NTOK;
        const int*   ri1 = rel_idx + i1 * NTOK;
        const float* mi0 = mrow + (size_t)i0 * NTOK;
        const float* mi1 = mrow + (size_t)i1 * NTOK;

        // ---- pass 1: scores into smem, track per-lane max ----
        float mx0 = -1e30f, mx1 = -1e30f;
        #pragma unroll
        for (int t = 0; t < 11; t++) {
            const int j = lane + 32 * t;
            if (j < NTOK) {
                const float* kr = &Ks[j * 36];
                float b0 = 0.f, b1 = 0.f, b2 = 0.f, b3 = 0.f;
                float c0 = 0.f, c1 = 0.f, c2 = 0.f, c3 = 0.f;
                #pragma unroll
                for (int u = 0; u < 8; u++) {
                    float4 kv = *(const float4*)(kr + u * 4);
                    b0 += q0[u].x * kv.x;  c0 += q1[u].x * kv.x;
                    b1 += q0[u].y * kv.y;  c1 += q1[u].y * kv.y;
                    b2 += q0[u].z * kv.z;  c2 += q1[u].z * kv.z;
                    b3 += q0[u].w * kv.w;  c3 += q1[u].w * kv.w;
                }
                float sc0 = (b0 + b1) + (b2 + b3);
                float sc1 = (c0 + c1) + (c2 + c3);
                sc0 += tab[__ldg(ri0 + j)] + __ldg(mi0 + j);
                sc1 += tab[__ldg(ri1 + j)] + __ldg(mi1 + j);
                ps0[j] = sc0;
                ps1[j] = sc1;
                mx0 = fmaxf(mx0, sc0);
                mx1 = fmaxf(mx1, sc1);
            }
        }
        #pragma unroll
        for (int off = 16; off; off >>= 1) {
            mx0 = fmaxf(mx0, __shfl_xor_sync(0xFFFFFFFFu, mx0, off));
            mx1 = fmaxf(mx1, __shfl_xor_sync(0xFFFFFFFFu, mx1, off));
        }
        __syncwarp();

        // ---- pass 2: scores -> probabilities, accumulate sums ----
        float sum0 = 0.f, sum1 = 0.f;
        #pragma unroll
        for (int t = 0; t < 11; t++) {
            const int j = lane + 32 * t;
            if (j < NTOK) {
                float p0 = exp2f((ps0[j] - mx0) * 1.4426950408889634f);
                float p1 = exp2f((ps1[j] - mx1) * 1.4426950408889634f);
                ps0[j] = p0;
                ps1[j] = p1;
                sum0 += p0;
                sum1 += p1;
            }
        }
        #pragma unroll
        for (int off = 16; off; off >>= 1) {
            sum0 += __shfl_xor_sync(0xFFFFFFFFu, sum0, off);
            sum1 += __shfl_xor_sync(0xFFFFFFFFu, sum1, off);
        }
        const float rinv0 = 1.f / sum0;
        const float rinv1 = 1.f / sum1;
        __syncwarp();

        // ---- PV: 4 lane-groups over j, each lane holds float4 accums for 2 rows ----
        float a0x = 0.f, a0y = 0.f, a0z = 0.f, a0w = 0.f;
        float a1x = 0.f, a1y = 0.f, a1z = 0.f, a1w = 0.f;
        #pragma unroll 5
        for (int jt = 0; jt < 85; jt++) {
            const int j = jt * 4 + g;              // j <= 339, always valid
            const float p0 = ps0[j];
            const float p1 = ps1[j];
            float4 v4 = *(const float4*)&Vs[j * 36 + dq * 4];
            a0x += p0 * v4.x; a0y += p0 * v4.y; a0z += p0 * v4.z; a0w += p0 * v4.w;
            a1x += p1 * v4.x; a1y += p1 * v4.y; a1z += p1 * v4.z; a1w += p1 * v4.w;
        }
        {   // tail: j = 340..342 (g == 3 invalid)
            const int j = 340 + g;
            if (j < NTOK) {
                const float p0 = ps0[j];
                const float p1 = ps1[j];
                float4 v4 = *(const float4*)&Vs[j * 36 + dq * 4];
                a0x += p0 * v4.x; a0y += p0 * v4.y; a0z += p0 * v4.z; a0w += p0 * v4.w;
                a1x += p1 * v4.x; a1y += p1 * v4.y; a1z += p1 * v4.z; a1w += p1 * v4.w;
            }
        }
        // combine the 4 j-groups (after this every lane has the full sums)
        #pragma unroll
        for (int off = 8; off <= 16; off <<= 1) {
            a0x += __shfl_xor_sync(0xFFFFFFFFu, a0x, off);
            a0y += __shfl_xor_sync(0xFFFFFFFFu, a0y, off);
            a0z += __shfl_xor_sync(0xFFFFFFFFu, a0z, off);
            a0w += __shfl_xor_sync(0xFFFFFFFFu, a0w, off);
            a1x += __shfl_xor_sync(0xFFFFFFFFu, a1x, off);
            a1y += __shfl_xor_sync(0xFFFFFFFFu, a1y, off);
            a1z += __shfl_xor_sync(0xFFFFFFFFu, a1z, off);
            a1w += __shfl_xor_sync(0xFFFFFFFFu, a1w, off);
        }

        if (lane < 8) {          // write row 0 (lane == dq)
            float4 ov = make_float4(a0x * rinv0, a0y * rinv0, a0z * rinv0, a0w * rinv0);
            *(float4*)&po[(size_t)i0 * CDIM + dq * 4] = ov;
        } else if (lane < 16 && valid1) {   // write row 1 (dq = lane-8)
            float4 ov = make_float4(a1x * rinv1, a1y * rinv1, a1z * rinv1, a1w * rinv1);
            *(float4*)&po[(size_t)i1r * CDIM + dq * 4] = ov;
        }
        __syncwarp();   // protect ps0/ps1 before next pair's writes
    }
}

// =================================================================================
// Kernel 3: out = g_o @ proj_w + proj_b. A: (87808 x 256), B: (256 x 256).
// Same BM=128, BN=128, BK=8 double-buffered template.
// =================================================================================
__global__ __launch_bounds__(256) void proj_gemm_kernel(
    const float* __restrict__ w,
    const float* __restrict__ bias,
    float* __restrict__ out)
{
    __shared__ float As[2][8][132];
    __shared__ float Bs[2][8][132];

    const int tid = threadIdx.x;
    const int tx  = tid & 15;
    const int ty  = tid >> 4;
    const int m0  = blockIdx.x * 128;
    const int n0  = blockIdx.y * 128;

    const int arow = tid >> 1;
    const int akg  = (tid & 1) * 4;
    const int brow = tid >> 5;
    const int bc   = (tid & 31) * 4;

    const float* ap = g_o + (size_t)(m0 + arow) * 256 + akg;
    const float* bp = w + (size_t)brow * 256 + n0 + bc;

    float acc[8][8];
    #pragma unroll
    for (int u = 0; u < 8; u++)
        #pragma unroll
        for (int v = 0; v < 8; v++) acc[u][v] = 0.f;

    {
        float4 av = *(const float4*)(ap);
        float4 bv = *(const float4*)(bp);
        As[0][akg + 0][arow] = av.x;
        As[0][akg + 1][arow] = av.y;
        As[0][akg + 2][arow] = av.z;
        As[0][akg + 3][arow] = av.w;
        *(float4*)&Bs[0][brow][bc] = bv;
    }
    __syncthreads();

    int cur = 0;
    for (int k0 = 0; k0 < 256; k0 += 8) {
        const bool has_next = (k0 + 8) < 256;
        float4 anx, bnx;
        if (has_next) {
            anx = *(const float4*)(ap + k0 + 8);
            bnx = *(const float4*)(bp + (size_t)(k0 + 8) * 256);
        }

        #pragma unroll
        for (int kk = 0; kk < 8; kk++) {
            float a[8], b[8];
            *(float4*)(a)     = *(const float4*)&As[cur][kk][ty * 8];
            *(float4*)(a + 4) = *(const float4*)&As[cur][kk][ty * 8 + 4];
            *(float4*)(b)     = *(const float4*)&Bs[cur][kk][tx * 8];
            *(float4*)(b + 4) = *(const float4*)&Bs[cur][kk][tx * 8 + 4];
            #pragma unroll
            for (int u = 0; u < 8; u++)
                #pragma unroll
                for (int v = 0; v < 8; v++) acc[u][v] += a[u] * b[v];
        }

        if (has_next) {
            const int nxt = cur ^ 1;
            As[nxt][akg + 0][arow] = anx.x;
            As[nxt][akg + 1][arow] = anx.y;
            As[nxt][akg + 2][arow] = anx.z;
            As[nxt][akg + 3][arow] = anx.w;
            *(float4*)&Bs[nxt][brow][bc] = bnx;
            __syncthreads();
            cur = nxt;
        }
    }

    #pragma unroll
    for (int u = 0; u < 8; u++) {
        const int r = m0 + ty * 8 + u;
        #pragma unroll
        for (int v0 = 0; v0 < 8; v0 += 4) {
            const int c = n0 + tx * 8 + v0;
            float4 vv;
            vv.x = acc[u][v0 + 0] + bias[c + 0];
            vv.y = acc[u][v0 + 1] + bias[c + 1];
            vv.z = acc[u][v0 + 2] + bias[c + 2];
            vv.w = acc[u][v0 + 3] + bias[c + 3];
            *(float4*)&out[(size_t)r * 256 + c] = vv;
        }
    }
}

// =================================================================================
extern "C" void kernel_launch(void* const* d_in, const int* in_sizes, int n_in,
                              void* d_out, int out_size)
{
    const float* x       = (const float*)d_in[0];
    const float* mask    = (const float*)d_in[1];
    const float* qkv_w   = (const float*)d_in[2];
    const float* qkv_b   = (const float*)d_in[3];
    const float* proj_w  = (const float*)d_in[4];
    const float* proj_b  = (const float*)d_in[5];
    const float* rpb     = (const float*)d_in[6];
    const int*   rel_idx = (const int*)d_in[7];
    float* out = (float*)d_out;

    // 1) QKV projection + scatter
    qkv_gemm_kernel<<<dim3(686, 6), 256>>>(x, qkv_w, qkv_b);

    // 2) fused window attention (2-row blocked)
    const size_t smem_bytes =
        (size_t)(NTOK * 36 * 2 + 2197 + 16 * 2 * NTOK) * sizeof(float);  // ~151.5 KB
    cudaFuncSetAttribute(attn_kernel,
                         cudaFuncAttributeMaxDynamicSharedMemorySize,
                         (int)smem_bytes);
    attn_kernel<<<BWIN * NHEAD, 512, smem_bytes>>>(mask, rpb, rel_idx);

    // 3) output projection
    proj_gemm_kernel<<<dim3(686, 2), 256>>>(proj_w, proj_b, out);
}

// round 11
// speedup vs baseline: 1.5147x; 1.1009x over previous
#include <cuda_runtime.h>
#include <cstdint>

#define NTOK  343
#define NPAD  352          // padded j-extent for PV (16-divisible)
#define NHEAD 8
#define CDIM  256
#define HD    32
#define BWIN  256
#define NWND  64
#define NN    (NTOK * NTOK)   // 117649
#define QSCALE 0.17677669529663687f   // 32^-0.5

// ---------------- scratch (device globals: no allocation allowed) ----------------
__device__ float g_q[(size_t)BWIN * NHEAD * NTOK * HD];   // scaled q, (Bw,H,n,hd)
__device__ float g_k[(size_t)BWIN * NHEAD * NTOK * HD];
__device__ float g_v[(size_t)BWIN * NHEAD * NTOK * HD];
__device__ float g_o[(size_t)BWIN * NTOK * CDIM];         // attention out, (Bw,n,C)
__device__ float g_bias[(size_t)NHEAD * NN];              // gathered rpb bias (H,n,n)

// =================================================================================
// Kernel 0: gather relative-position bias: g_bias[h][p] = rpb[rel_idx[p]*8 + h]
// =================================================================================
__global__ __launch_bounds__(256) void bias_gather_kernel(
    const float* __restrict__ rpb,
    const int*   __restrict__ rel_idx)
{
    const int p = blockIdx.x * 256 + threadIdx.x;
    if (p >= NN) return;
    const int idx = rel_idx[p];
    float4 r0 = *(const float4*)(rpb + (size_t)idx * 8);
    float4 r1 = *(const float4*)(rpb + (size_t)idx * 8 + 4);
    g_bias[0 * (size_t)NN + p] = r0.x;
    g_bias[1 * (size_t)NN + p] = r0.y;
    g_bias[2 * (size_t)NN + p] = r0.z;
    g_bias[3 * (size_t)NN + p] = r0.w;
    g_bias[4 * (size_t)NN + p] = r1.x;
    g_bias[5 * (size_t)NN + p] = r1.y;
    g_bias[6 * (size_t)NN + p] = r1.z;
    g_bias[7 * (size_t)NN + p] = r1.w;
}

// =================================================================================
// Kernel 1: QKV = x @ qkv_w + qkv_b, scatter to g_q (scaled), g_k, g_v
// A: (87808 x 256), B: (256 x 768). BM=128, BN=128, BK=8 double-buffered (x2 unroll)
// =================================================================================
__global__ __launch_bounds__(256) void qkv_gemm_kernel(
    const float* __restrict__ x,
    const float* __restrict__ w,
    const float* __restrict__ bias)
{
    __shared__ float As[2][8][132];
    __shared__ float Bs[2][8][132];

    const int tid = threadIdx.x;
    const int tx  = tid & 15;      // n direction (16)
    const int ty  = tid >> 4;      // m direction (16)
    const int m0  = blockIdx.x * 128;
    const int n0  = blockIdx.y * 128;

    const int arow = tid >> 1;            // 0..127
    const int akg  = (tid & 1) * 4;       // 0 or 4
    const int brow = tid >> 5;            // 0..7
    const int bc   = (tid & 31) * 4;      // 0..124

    const float* ap = x + (size_t)(m0 + arow) * 256 + akg;
    const float* bp = w + (size_t)brow * 768 + n0 + bc;

    float acc[8][8];
    #pragma unroll
    for (int u = 0; u < 8; u++)
        #pragma unroll
        for (int v = 0; v < 8; v++) acc[u][v] = 0.f;

#define QKV_STAGE(BUF, KK)                                                  \
    {                                                                       \
        float a[8], b[8];                                                   \
        *(float4*)(a)     = *(const float4*)&As[BUF][KK][ty * 8];           \
        *(float4*)(a + 4) = *(const float4*)&As[BUF][KK][ty * 8 + 4];       \
        *(float4*)(b)     = *(const float4*)&Bs[BUF][KK][tx * 8];           \
        *(float4*)(b + 4) = *(const float4*)&Bs[BUF][KK][tx * 8 + 4];       \
        _Pragma("unroll")                                                   \
        for (int u = 0; u < 8; u++)                                         \
            _Pragma("unroll")                                               \
            for (int v = 0; v < 8; v++) acc[u][v] += a[u] * b[v];           \
    }
#define QKV_COMPUTE(BUF)                                                    \
    { _Pragma("unroll") for (int kk = 0; kk < 8; kk++) QKV_STAGE(BUF, kk) }
#define QKV_STORE(BUF, AV, BV)                                              \
    {                                                                       \
        As[BUF][akg + 0][arow] = (AV).x;                                    \
        As[BUF][akg + 1][arow] = (AV).y;                                    \
        As[BUF][akg + 2][arow] = (AV).z;                                    \
        As[BUF][akg + 3][arow] = (AV).w;                                    \
        *(float4*)&Bs[BUF][brow][bc] = (BV);                                \
    }

    // prologue: tile 0 -> buf0
    {
        float4 av = *(const float4*)(ap);
        float4 bv = *(const float4*)(bp);
        QKV_STORE(0, av, bv);
    }
    __syncthreads();

    for (int k0 = 0; k0 < 256; k0 += 16) {
        // stage A: compute buf0 (tile k0/8), prefetch tile k0+8 -> buf1
        {
            float4 av = *(const float4*)(ap + k0 + 8);
            float4 bv = *(const float4*)(bp + (size_t)(k0 + 8) * 768);
            QKV_COMPUTE(0);
            QKV_STORE(1, av, bv);
            __syncthreads();
        }
        // stage B: compute buf1 (tile k0/8+1), prefetch tile k0+16 -> buf0
        {
            const bool hn = (k0 + 16) < 256;
            float4 av, bv;
            if (hn) {
                av = *(const float4*)(ap + k0 + 16);
                bv = *(const float4*)(bp + (size_t)(k0 + 16) * 768);
            }
            QKV_COMPUTE(1);
            if (hn) {
                QKV_STORE(0, av, bv);
                __syncthreads();
            }
        }
    }

    // epilogue: bias, scale q, scatter to (Bw,H,n,hd)
    #pragma unroll
    for (int u = 0; u < 8; u++) {
        const int r  = m0 + ty * 8 + u;
        const int bw = r / NTOK;
        const int i  = r - bw * NTOK;
        #pragma unroll
        for (int v0 = 0; v0 < 8; v0 += 4) {
            const int c    = n0 + tx * 8 + v0;
            const int part = c >> 8;          // uniform per block (n0 multiple of 128)
            const int cc   = c & 255;
            const int h    = cc >> 5;
            const int d    = cc & 31;
            float4 vv;
            vv.x = acc[u][v0 + 0] + bias[c + 0];
            vv.y = acc[u][v0 + 1] + bias[c + 1];
            vv.z = acc[u][v0 + 2] + bias[c + 2];
            vv.w = acc[u][v0 + 3] + bias[c + 3];
            float* dst;
            if (part == 0) {
                vv.x *= QSCALE; vv.y *= QSCALE; vv.z *= QSCALE; vv.w *= QSCALE;
                dst = g_q;
            } else {
                dst = (part == 1) ? g_k : g_v;
            }
            *(float4*)&dst[(size_t)((bw * NHEAD + h) * NTOK + i) * HD + d] = vv;
        }
    }
}

// =================================================================================
// Kernel 2: fused attention, 2-row register blocking per warp, vectorized PV.
// One block = one (bw, head). 512 threads (16 warps).
// smem: K(343x36), V(352x36 zero-padded), p-buffers (16 x 2 x 352 zero-padded).
// =================================================================================
__global__ __launch_bounds__(512) void attn_kernel(
    const float* __restrict__ mask)
{
    extern __shared__ float sm[];
    float* Ks  = sm;                      // 343*36
    float* Vs  = Ks + NTOK * 36;          // 352*36
    float* ps  = Vs + NPAD * 36;          // 16*2*352

    const int bx = blockIdx.x;
    const int bw = bx >> 3;
    const int h  = bx & 7;
    const int tid = threadIdx.x;

    const float* kb = g_k + (size_t)(bw * NHEAD + h) * NTOK * HD;
    const float* vb = g_v + (size_t)(bw * NHEAD + h) * NTOK * HD;

    // ---- cooperative load of K, V (padded); zero V pad rows and all p-buffers ----
    for (int idx = tid; idx < NPAD * 8; idx += 512) {
        const int row = idx >> 3;
        const int c4  = idx & 7;
        if (row < NTOK) {
            float4 kv = ((const float4*)kb)[idx];
            *(float4*)&Ks[row * 36 + c4 * 4] = kv;
            float4 vv = ((const float4*)vb)[idx];
            *(float4*)&Vs[row * 36 + c4 * 4] = vv;
        } else {
            *(float4*)&Vs[row * 36 + c4 * 4] = make_float4(0.f, 0.f, 0.f, 0.f);
        }
    }
    for (int idx = tid; idx < 16 * 2 * NPAD; idx += 512) ps[idx] = 0.f;
    __syncthreads();

    const int warp = tid >> 5;
    const int lane = tid & 31;
    const int g    = lane >> 3;   // j-group (0..3)
    const int dq   = lane & 7;    // float4 index into head dim

    const float* qb   = g_q + (size_t)(bw * NHEAD + h) * NTOK * HD;
    const float* mrow = mask + (size_t)(bw & (NWND - 1)) * NN;
    const float* brow = g_bias + (size_t)h * NN;
    float*       po   = g_o + (size_t)bw * NTOK * CDIM + h * HD;
    float*       ps0  = ps + warp * 2 * NPAD;
    float*       ps1  = ps0 + NPAD;

    for (int ib = warp; ib < (NTOK + 1) / 2; ib += 16) {
        const int i0  = 2 * ib;
        const int i1r = 2 * ib + 1;
        const bool valid1 = (i1r < NTOK);
        const int i1 = valid1 ? i1r : (NTOK - 1);

        // q rows into registers (broadcast loads)
        float4 q0[8], q1[8];
        {
            const float4* qp0 = (const float4*)(qb + i0 * HD);
            const float4* qp1 = (const float4*)(qb + i1 * HD);
            #pragma unroll
            for (int u = 0; u < 8; u++) { q0[u] = qp0[u]; q1[u] = qp1[u]; }
        }

        const float* bi0 = brow + (size_t)i0 * NTOK;
        const float* bi1 = brow + (size_t)i1 * NTOK;
        const float* mi0 = mrow + (size_t)i0 * NTOK;
        const float* mi1 = mrow + (size_t)i1 * NTOK;

        // ---- pass 1: scores into smem, track per-lane max ----
        float mx0 = -1e30f, mx1 = -1e30f;
        #pragma unroll
        for (int t = 0; t < 11; t++) {
            const int j = lane + 32 * t;
            if (j < NTOK) {
                const float* kr = &Ks[j * 36];
                float b0 = 0.f, b1 = 0.f, b2 = 0.f, b3 = 0.f;
                float c0 = 0.f, c1 = 0.f, c2 = 0.f, c3 = 0.f;
                #pragma unroll
                for (int u = 0; u < 8; u++) {
                    float4 kv = *(const float4*)(kr + u * 4);
                    b0 += q0[u].x * kv.x;  c0 += q1[u].x * kv.x;
                    b1 += q0[u].y * kv.y;  c1 += q1[u].y * kv.y;
                    b2 += q0[u].z * kv.z;  c2 += q1[u].z * kv.z;
                    b3 += q0[u].w * kv.w;  c3 += q1[u].w * kv.w;
                }
                float sc0 = (b0 + b1) + (b2 + b3);
                float sc1 = (c0 + c1) + (c2 + c3);
                sc0 += __ldg(bi0 + j) + __ldg(mi0 + j);
                sc1 += __ldg(bi1 + j) + __ldg(mi1 + j);
                ps0[j] = sc0;
                ps1[j] = sc1;
                mx0 = fmaxf(mx0, sc0);
                mx1 = fmaxf(mx1, sc1);
            }
        }
        #pragma unroll
        for (int off = 16; off; off >>= 1) {
            mx0 = fmaxf(mx0, __shfl_xor_sync(0xFFFFFFFFu, mx0, off));
            mx1 = fmaxf(mx1, __shfl_xor_sync(0xFFFFFFFFu, mx1, off));
        }
        __syncwarp();

        // ---- pass 2: scores -> probabilities, accumulate sums ----
        float sum0 = 0.f, sum1 = 0.f;
        #pragma unroll
        for (int t = 0; t < 11; t++) {
            const int j = lane + 32 * t;
            if (j < NTOK) {
                float p0 = exp2f((ps0[j] - mx0) * 1.4426950408889634f);
                float p1 = exp2f((ps1[j] - mx1) * 1.4426950408889634f);
                ps0[j] = p0;
                ps1[j] = p1;
                sum0 += p0;
                sum1 += p1;
            }
        }
        #pragma unroll
        for (int off = 16; off; off >>= 1) {
            sum0 += __shfl_xor_sync(0xFFFFFFFFu, sum0, off);
            sum1 += __shfl_xor_sync(0xFFFFFFFFu, sum1, off);
        }
        const float rinv0 = 1.f / sum0;
        const float rinv1 = 1.f / sum1;
        __syncwarp();

        // ---- PV: 4 lane-groups x 4 consecutive j per iteration (vectorized p) ----
        float a0x = 0.f, a0y = 0.f, a0z = 0.f, a0w = 0.f;
        float a1x = 0.f, a1y = 0.f, a1z = 0.f, a1w = 0.f;
        #pragma unroll 2
        for (int jt = 0; jt < NPAD / 16; jt++) {       // 22 iterations
            const int j0 = jt * 16 + g * 4;
            float4 p0 = *(const float4*)&ps0[j0];
            float4 p1 = *(const float4*)&ps1[j0];
            float4 v0 = *(const float4*)&Vs[(j0 + 0) * 36 + dq * 4];
            float4 v1 = *(const float4*)&Vs[(j0 + 1) * 36 + dq * 4];
            float4 v2 = *(const float4*)&Vs[(j0 + 2) * 36 + dq * 4];
            float4 v3 = *(const float4*)&Vs[(j0 + 3) * 36 + dq * 4];
            a0x += p0.x * v0.x; a0y += p0.x * v0.y; a0z += p0.x * v0.z; a0w += p0.x * v0.w;
            a1x += p1.x * v0.x; a1y += p1.x * v0.y; a1z += p1.x * v0.z; a1w += p1.x * v0.w;
            a0x += p0.y * v1.x; a0y += p0.y * v1.y; a0z += p0.y * v1.z; a0w += p0.y * v1.w;
            a1x += p1.y * v1.x; a1y += p1.y * v1.y; a1z += p1.y * v1.z; a1w += p1.y * v1.w;
            a0x += p0.z * v2.x; a0y += p0.z * v2.y; a0z += p0.z * v2.z; a0w += p0.z * v2.w;
            a1x += p1.z * v2.x; a1y += p1.z * v2.y; a1z += p1.z * v2.z; a1w += p1.z * v2.w;
            a0x += p0.w * v3.x; a0y += p0.w * v3.y; a0z += p0.w * v3.z; a0w += p0.w * v3.w;
            a1x += p1.w * v3.x; a1y += p1.w * v3.y; a1z += p1.w * v3.z; a1w += p1.w * v3.w;
        }
        // combine the 4 j-groups (after this every lane has the full sums)
        #pragma unroll
        for (int off = 8; off <= 16; off <<= 1) {
            a0x += __shfl_xor_sync(0xFFFFFFFFu, a0x, off);
            a0y += __shfl_xor_sync(0xFFFFFFFFu, a0y, off);
            a0z += __shfl_xor_sync(0xFFFFFFFFu, a0z, off);
            a0w += __shfl_xor_sync(0xFFFFFFFFu, a0w, off);
            a1x += __shfl_xor_sync(0xFFFFFFFFu, a1x, off);
            a1y += __shfl_xor_sync(0xFFFFFFFFu, a1y, off);
            a1z += __shfl_xor_sync(0xFFFFFFFFu, a1z, off);
            a1w += __shfl_xor_sync(0xFFFFFFFFu, a1w, off);
        }

        if (lane < 8) {          // write row 0 (lane == dq)
            float4 ov = make_float4(a0x * rinv0, a0y * rinv0, a0z * rinv0, a0w * rinv0);
            *(float4*)&po[(size_t)i0 * CDIM + dq * 4] = ov;
        } else if (lane < 16 && valid1) {   // write row 1 (dq = lane-8)
            float4 ov = make_float4(a1x * rinv1, a1y * rinv1, a1z * rinv1, a1w * rinv1);
            *(float4*)&po[(size_t)i1r * CDIM + dq * 4] = ov;
        }
        __syncwarp();   // protect ps0/ps1 before next pair's writes
    }
}

// =================================================================================
// Kernel 3: out = g_o @ proj_w + proj_b. A: (87808 x 256), B: (256 x 256).
// =================================================================================
__global__ __launch_bounds__(256) void proj_gemm_kernel(
    const float* __restrict__ w,
    const float* __restrict__ bias,
    float* __restrict__ out)
{
    __shared__ float As[2][8][132];
    __shared__ float Bs[2][8][132];

    const int tid = threadIdx.x;
    const int tx  = tid & 15;
    const int ty  = tid >> 4;
    const int m0  = blockIdx.x * 128;
    const int n0  = blockIdx.y * 128;

    const int arow = tid >> 1;
    const int akg  = (tid & 1) * 4;
    const int brow = tid >> 5;
    const int bc   = (tid & 31) * 4;

    const float* ap = g_o + (size_t)(m0 + arow) * 256 + akg;
    const float* bp = w + (size_t)brow * 256 + n0 + bc;

    float acc[8][8];
    #pragma unroll
    for (int u = 0; u < 8; u++)
        #pragma unroll
        for (int v = 0; v < 8; v++) acc[u][v] = 0.f;

    {
        float4 av = *(const float4*)(ap);
        float4 bv = *(const float4*)(bp);
        QKV_STORE(0, av, bv);
    }
    __syncthreads();

    for (int k0 = 0; k0 < 256; k0 += 16) {
        {
            float4 av = *(const float4*)(ap + k0 + 8);
            float4 bv = *(const float4*)(bp + (size_t)(k0 + 8) * 256);
            QKV_COMPUTE(0);
            QKV_STORE(1, av, bv);
            __syncthreads();
        }
        {
            const bool hn = (k0 + 16) < 256;
            float4 av, bv;
            if (hn) {
                av = *(const float4*)(ap + k0 + 16);
                bv = *(const float4*)(bp + (size_t)(k0 + 16) * 256);
            }
            QKV_COMPUTE(1);
            if (hn) {
                QKV_STORE(0, av, bv);
                __syncthreads();
            }
        }
    }

    #pragma unroll
    for (int u = 0; u < 8; u++) {
        const int r = m0 + ty * 8 + u;
        #pragma unroll
        for (int v0 = 0; v0 < 8; v0 += 4) {
            const int c = n0 + tx * 8 + v0;
            float4 vv;
            vv.x = acc[u][v0 + 0] + bias[c + 0];
            vv.y = acc[u][v0 + 1] + bias[c + 1];
            vv.z = acc[u][v0 + 2] + bias[c + 2];
            vv.w = acc[u][v0 + 3] + bias[c + 3];
            *(float4*)&out[(size_t)r * 256 + c] = vv;
        }
    }
}

// =================================================================================
extern "C" void kernel_launch(void* const* d_in, const int* in_sizes, int n_in,
                              void* d_out, int out_size)
{
    const float* x       = (const float*)d_in[0];
    const float* mask    = (const float*)d_in[1];
    const float* qkv_w   = (const float*)d_in[2];
    const float* qkv_b   = (const float*)d_in[3];
    const float* proj_w  = (const float*)d_in[4];
    const float* proj_b  = (const float*)d_in[5];
    const float* rpb     = (const float*)d_in[6];
    const int*   rel_idx = (const int*)d_in[7];
    float* out = (float*)d_out;

    // 0) bias gather (independent of GEMM)
    bias_gather_kernel<<<(NN + 255) / 256, 256>>>(rpb, rel_idx);

    // 1) QKV projection + scatter
    qkv_gemm_kernel<<<dim3(686, 6), 256>>>(x, qkv_w, qkv_b);

    // 2) fused window attention (2-row blocked, vectorized PV)
    const size_t smem_bytes =
        (size_t)(NTOK * 36 + NPAD * 36 + 16 * 2 * NPAD) * sizeof(float);  // ~142 KB
    cudaFuncSetAttribute(attn_kernel,
                         cudaFuncAttributeMaxDynamicSharedMemorySize,
                         (int)smem_bytes);
    attn_kernel<<<BWIN * NHEAD, 512, smem_bytes>>>(mask);

    // 3) output projection
    proj_gemm_kernel<<<dim3(686, 2), 256>>>(proj_w, proj_b, out);
}